// round 14
// baseline (speedup 1.0000x reference)
#include <cuda_runtime.h>

#define SEQ_LEN 131072
#define IN 100
#define HID 40
#define PF 8                          // xs prefetch depth (ring in registers)

#define NCHUNK 1024
#define CHLEN (SEQ_LEN / NCHUNK)      // 128 steps owned per chunk
#define BURN 64                       // burn-in steps (discarded)

#define XTT 64                        // timesteps per block in k_xproj
#define NXT (SEQ_LEN / XTT)           // 2048 xproj tiles
#define TJ 5                          // outputs per thread (8 j-groups)
#define TT 4                          // timesteps per thread (16 t-groups)
#define SP 102                        // padded sS row stride (floats): conflict-free

#define NL 25                         // active lanes in k_out (own 4 outputs each)
#define NQ (HID / 2)                  // 20 k-pairs
#define OT 32                         // timesteps per k_out tile
#define NTILE (SEQ_LEN / OT)          // 4096 tiles
#define KOUT_GRID 148                 // 1 persistent k_out block per SM

typedef unsigned long long u64;

// Scratch: device globals (no allocations allowed)
__device__ float g_xs[(SEQ_LEN + PF) * HID];  // input projections (+PF pad rows)
__device__ float g_h[SEQ_LEN * HID];          // hidden states per step
__device__ unsigned g_xdone[NXT];             // xproj tile completion flags
__device__ unsigned g_hdone[NCHUNK];          // recur chunk completion flags

// ---- packed f32x2 + sync helpers (sm_103a) ---------------------------------
__device__ __forceinline__ u64 ffma2(u64 a, u64 b, u64 c) {
    u64 d; asm("fma.rn.f32x2 %0, %1, %2, %3;" : "=l"(d) : "l"(a), "l"(b), "l"(c));
    return d;
}
__device__ __forceinline__ u64 fadd2(u64 a, u64 b) {
    u64 d; asm("add.rn.f32x2 %0, %1, %2;" : "=l"(d) : "l"(a), "l"(b));
    return d;
}
__device__ __forceinline__ float hsum2(u64 a) {
    unsigned lo, hi; asm("mov.b64 {%0, %1}, %2;" : "=r"(lo), "=r"(hi) : "l"(a));
    return __uint_as_float(lo) + __uint_as_float(hi);
}
__device__ __forceinline__ float mufu_tanh(float x) {
    float r; asm("tanh.approx.f32 %0, %1;" : "=f"(r) : "f"(x));
    return r;
}
__device__ __forceinline__ void st_release(unsigned* p, unsigned v) {
    asm volatile("st.release.gpu.u32 [%0], %1;" :: "l"(p), "r"(v) : "memory");
}
__device__ __forceinline__ unsigned ld_acquire(const unsigned* p) {
    unsigned v; asm volatile("ld.acquire.gpu.u32 %0, [%1];" : "=r"(v) : "l"(p) : "memory");
    return v;
}

// ---------------------------------------------------------------------------
// Kernel 1: xs[t] = Wx @ s[t] + Wx_b — 2-D register tile (5 outs x 4 steps),
// sS padded to 102 floats/row -> tg banks {0,24,16,8}: conflict-free LDS.64.
// Sets g_xdone[tile] when done.
// ---------------------------------------------------------------------------
__global__ void __launch_bounds__(128)
k_xproj(const float* __restrict__ s,
        const float* __restrict__ Wx,
        const float* __restrict__ Wxb) {
    cudaTriggerProgrammaticLaunchCompletion();

    __shared__ __align__(16) float sW[HID * IN];     // 16 KB
    __shared__ __align__(16) float sS[XTT * SP];     // 26.1 KB (padded rows)
    __shared__ float sb[HID];

    const int tid  = threadIdx.x;
    const int base = blockIdx.x * XTT;

    {
        const float4* wg = reinterpret_cast<const float4*>(Wx);
        float4*       ws = reinterpret_cast<float4*>(sW);
#pragma unroll
        for (int i = tid; i < HID * IN / 4; i += 128) ws[i] = wg[i];

        const float2* sg = reinterpret_cast<const float2*>(s + base * IN);
        for (int m = tid; m < XTT * IN / 2; m += 128) {
            const int row = m / (IN / 2), c2 = m % (IN / 2);
            *reinterpret_cast<float2*>(sS + row * SP + 2 * c2) = sg[m];
        }
        if (tid < HID) sb[tid] = Wxb[tid];
    }
    __syncthreads();

    const int jg = tid & 7;            // 8 j-groups
    const int tg = tid >> 3;           // 16 t-groups
    const int j0 = jg * TJ;
    const int t0 = tg * TT;

    u64 acc[TJ][TT];
#pragma unroll
    for (int jj = 0; jj < TJ; jj++)
#pragma unroll
        for (int i = 0; i < TT; i++) acc[jj][i] = 0ull;

#pragma unroll
    for (int q = 0; q < IN / 4; q++) {       // 25 k-quads
        ulonglong2 w[TJ];
#pragma unroll
        for (int jj = 0; jj < TJ; jj++)
            w[jj] = *reinterpret_cast<const ulonglong2*>(sW + (j0 + jj) * IN + 4 * q);
        u64 sa[TT], sc[TT];
#pragma unroll
        for (int i = 0; i < TT; i++) {
            const float* sr = sS + (t0 + i) * SP + 4 * q;
            sa[i] = *reinterpret_cast<const u64*>(sr);       // k = 4q, 4q+1
            sc[i] = *reinterpret_cast<const u64*>(sr + 2);   // k = 4q+2, 4q+3
        }
#pragma unroll
        for (int jj = 0; jj < TJ; jj++)
#pragma unroll
            for (int i = 0; i < TT; i++) {
                acc[jj][i] = ffma2((u64)w[jj].x, sa[i], acc[jj][i]);
                acc[jj][i] = ffma2((u64)w[jj].y, sc[i], acc[jj][i]);
            }
    }

#pragma unroll
    for (int jj = 0; jj < TJ; jj++) {
        const float bj = sb[j0 + jj];
#pragma unroll
        for (int i = 0; i < TT; i++)
            g_xs[(base + t0 + i) * HID + j0 + jj] = hsum2(acc[jj][i]) + bj;
    }

    __threadfence();
    __syncthreads();
    if (tid == 0) st_release(&g_xdone[blockIdx.x], 1u);
}

// ---------------------------------------------------------------------------
// Kernel 2: chunked recurrence — single warp per chunk (proven R12), PDL:
// waits on g_xdone tiles it needs, sets g_hdone[c] when its h range is out.
// ---------------------------------------------------------------------------
__global__ void __launch_bounds__(32, 16)
k_recur(const float* __restrict__ Wh,  const float* __restrict__ Whb,
        const float* __restrict__ h0,  float* __restrict__ hfinal) {
    cudaTriggerProgrammaticLaunchCompletion();

    const int c    = blockIdx.x;
    const int lane = threadIdx.x;          // 0..31

    const bool act = (lane < HID / 2);     // 20 active lanes
    const int  j1  = act ? lane : (HID / 2 - 1);
    const int  j2  = j1 + HID / 2;

    const int t_own = c * CHLEN;
    const int t_lo  = (t_own >= BURN) ? (t_own - BURN) : 0;
    const int t_hi  = t_own + CHLEN;

    // wait for the xs tiles this chunk touches (incl. prefetch reach)
    {
        const int tl_lo = t_lo >> 6;
        int tl_hi = (t_hi - 1 + PF) >> 6;
        if (tl_hi > NXT - 1) tl_hi = NXT - 1;
        for (int tl = tl_lo; tl <= tl_hi; tl++)
            while (ld_acquire(&g_xdone[tl]) == 0) __nanosleep(64);
    }

    __shared__ __align__(16) float hs[2][HID];

    u64 w1[HID / 2], w2[HID / 2];
    {
        const longlong2* r1 = reinterpret_cast<const longlong2*>(Wh + j1 * HID);
        const longlong2* r2 = reinterpret_cast<const longlong2*>(Wh + j2 * HID);
#pragma unroll
        for (int q = 0; q < HID / 4; q++) {     // 10 iters
            longlong2 a = r1[q], b = r2[q];
            w1[2 * q] = (u64)a.x;  w1[2 * q + 1] = (u64)a.y;
            w2[2 * q] = (u64)b.x;  w2[2 * q + 1] = (u64)b.y;
        }
    }
    const float b1 = Whb[j1];
    const float b2 = Whb[j2];

    if (act) {
        hs[0][j1] = (c == 0) ? h0[j1] : 0.f;
        hs[0][j2] = (c == 0) ? h0[j2] : 0.f;
    }
    __syncwarp();

    float xf1[PF], xf2[PF];
#pragma unroll
    for (int k = 0; k < PF; k++) {
        xf1[k] = g_xs[(t_lo + k) * HID + j1];
        xf2[k] = g_xs[(t_lo + k) * HID + j2];
    }

    float v1 = 0.f, v2 = 0.f;

    for (int tb = t_lo; tb < t_hi; tb += PF) {
#pragma unroll
        for (int k = 0; k < PF; k++) {
            const int t = tb + k;                   // t&1 == k&1 (t_lo, PF even)
            const longlong2* hc = reinterpret_cast<const longlong2*>(hs[k & 1]);
            u64 a0 = 0ull, a1 = 0ull, c0 = 0ull, c1 = 0ull;
#pragma unroll
            for (int q = 0; q < 10; q += 2) {
                const longlong2 h01 = hc[q];
                const longlong2 h23 = hc[q + 1];
                a0 = ffma2(w1[2 * q],     (u64)h01.x, a0);
                a1 = ffma2(w1[2 * q + 1], (u64)h01.y, a1);
                c0 = ffma2(w2[2 * q],     (u64)h01.x, c0);
                c1 = ffma2(w2[2 * q + 1], (u64)h01.y, c1);
                a0 = ffma2(w1[2 * q + 2], (u64)h23.x, a0);
                a1 = ffma2(w1[2 * q + 3], (u64)h23.y, a1);
                c0 = ffma2(w2[2 * q + 2], (u64)h23.x, c0);
                c1 = ffma2(w2[2 * q + 3], (u64)h23.y, c1);
            }
            const float z1 = hsum2(fadd2(a0, a1)) + (xf1[k] + b1);
            const float z2 = hsum2(fadd2(c0, c1)) + (xf2[k] + b2);
            v1 = mufu_tanh(z1);
            v2 = mufu_tanh(z2);

            xf1[k] = g_xs[(tb + k + PF) * HID + j1];   // refill (padded array)
            xf2[k] = g_xs[(tb + k + PF) * HID + j2];

            if (act) {
                hs[(k & 1) ^ 1][j1] = v1;
                hs[(k & 1) ^ 1][j2] = v2;
                if (t >= t_own) {
                    g_h[t * HID + j1] = v1;
                    g_h[t * HID + j2] = v2;
                }
            }
            __syncwarp();
        }
    }
    if (act && c == NCHUNK - 1) {
        hfinal[j1] = v1;
        hfinal[j2] = v2;
    }

    __threadfence();
    __syncwarp();
    if (lane == 0) st_release(&g_hdone[c], 1u);
}

// ---------------------------------------------------------------------------
// Kernel 3: ys[t] = softmax(Wy h_t + Wy_b) — persistent, PDL-overlapped with
// k_recur: spins on g_hdone[chunk] per tile (R2-proven acquire/release).
// ---------------------------------------------------------------------------
__global__ void __launch_bounds__(256)
k_out(const float* __restrict__ Wy, const float* __restrict__ Wyb,
      float* __restrict__ ys) {
    __shared__ __align__(16) u64   sWq[NQ * IN];     // 16 KB transposed weights
    __shared__ __align__(16) float sh[OT][HID];      // 5 KB h tile

    const int tid = threadIdx.x;

    for (int m = tid; m < NQ * IN; m += 256) {
        const int q = m / IN, j = m % IN;
        sWq[m] = *reinterpret_cast<const u64*>(Wy + j * HID + 2 * q);
    }

    const int lane = tid & 31;
    const int wrp  = tid >> 5;               // 0..7 owns timesteps [4w, 4w+4)
    const bool act = (lane < NL);            // 25 active lanes
    const int  j0  = act ? lane : 0;         // outputs j0, j0+25, j0+50, j0+75

    float bias[4];
#pragma unroll
    for (int n = 0; n < 4; n++) bias[n] = Wyb[j0 + NL * n];

    const int l0 = wrp * 4;

    for (int tile = blockIdx.x; tile < NTILE; tile += KOUT_GRID) {
        const int base = tile * OT;

        // wait for the recur chunk that owns this tile's h range
        while (ld_acquire(&g_hdone[tile >> 2]) == 0) __nanosleep(128);

        __syncthreads();                     // protect sh reuse across iters
        {
            const float4* hg = reinterpret_cast<const float4*>(g_h + base * HID);
            float4*       h4 = reinterpret_cast<float4*>(&sh[0][0]);
#pragma unroll
            for (int i = tid; i < OT * HID / 4; i += 256) h4[i] = hg[i];
        }
        __syncthreads();

        u64 a[4][4];                         // [output n][timestep i]
#pragma unroll
        for (int n = 0; n < 4; n++)
#pragma unroll
            for (int i = 0; i < 4; i++) a[n][i] = 0ull;

#pragma unroll
        for (int q = 0; q < NQ; q++) {
            u64 w0 = sWq[q * IN + j0];
            u64 w1 = sWq[q * IN + j0 + NL];
            u64 w2 = sWq[q * IN + j0 + 2 * NL];
            u64 w3 = sWq[q * IN + j0 + 3 * NL];
#pragma unroll
            for (int i = 0; i < 4; i++) {
                const u64 hq =
                    *reinterpret_cast<const u64*>(&sh[l0 + i][2 * q]); // broadcast
                a[0][i] = ffma2(w0, hq, a[0][i]);
                a[1][i] = ffma2(w1, hq, a[1][i]);
                a[2][i] = ffma2(w2, hq, a[2][i]);
                a[3][i] = ffma2(w3, hq, a[3][i]);
            }
        }

#pragma unroll
        for (int i = 0; i < 4; i++) {
            float e[4];
            float sum = 0.f;
#pragma unroll
            for (int n = 0; n < 4; n++) {
                const float z = hsum2(a[n][i]) + bias[n];
                e[n] = act ? __expf(z) : 0.f;
                sum += e[n];
            }
#pragma unroll
            for (int o = 16; o > 0; o >>= 1)
                sum += __shfl_xor_sync(0xffffffffu, sum, o);
            const float inv = __frcp_rn(sum);
            if (act) {
                float* y = ys + (base + l0 + i) * IN;
#pragma unroll
                for (int n = 0; n < 4; n++)
                    y[j0 + NL * n] = e[n] * inv;     // coalesced
            }
        }
    }
}

// ---------------------------------------------------------------------------
extern "C" void kernel_launch(void* const* d_in, const int* in_sizes, int n_in,
                              void* d_out, int out_size) {
    const float* s   = (const float*)d_in[0];
    const float* h0  = (const float*)d_in[1];
    const float* Wx  = (const float*)d_in[2];
    const float* Wxb = (const float*)d_in[3];
    const float* Wh  = (const float*)d_in[4];
    const float* Whb = (const float*)d_in[5];
    const float* Wy  = (const float*)d_in[6];
    const float* Wyb = (const float*)d_in[7];

    float* out    = (float*)d_out;
    float* hfinal = out;           // [40]
    float* ys     = out + HID;     // [SEQ_LEN, 100]

    // reset completion flags each replay (async memset: capturable, no alloc)
    void* px = nullptr; void* ph = nullptr;
    cudaGetSymbolAddress(&px, g_xdone);
    cudaGetSymbolAddress(&ph, g_hdone);
    cudaMemsetAsync(px, 0, NXT * sizeof(unsigned));
    cudaMemsetAsync(ph, 0, NCHUNK * sizeof(unsigned));

    k_xproj<<<NXT, 128>>>(s, Wx, Wxb);

    cudaLaunchAttribute attr[1];
    attr[0].id = cudaLaunchAttributeProgrammaticStreamSerialization;
    attr[0].val.programmaticStreamSerializationAllowed = 1;

    cudaLaunchConfig_t cfg_r = {};
    cfg_r.gridDim  = dim3(NCHUNK, 1, 1);
    cfg_r.blockDim = dim3(32, 1, 1);
    cfg_r.attrs    = attr;
    cfg_r.numAttrs = 1;
    cudaLaunchKernelEx(&cfg_r, k_recur, Wh, Whb, h0, hfinal);

    cudaLaunchConfig_t cfg_o = {};
    cfg_o.gridDim  = dim3(KOUT_GRID, 1, 1);
    cfg_o.blockDim = dim3(256, 1, 1);
    cfg_o.attrs    = attr;
    cfg_o.numAttrs = 1;
    cudaLaunchKernelEx(&cfg_o, k_out, Wy, Wyb, ys);
}

// round 15
// speedup vs baseline: 1.5281x; 1.5281x over previous
#include <cuda_runtime.h>

#define SEQ_LEN 131072
#define IN 100
#define HID 40
#define PF 8                          // xs prefetch depth (ring in registers)

#define NCHUNK 1024
#define CHLEN (SEQ_LEN / NCHUNK)      // 128 steps owned per chunk
#define BURN 32                       // burn-in steps (discarded)

#define XTT 64                        // timesteps per block in k_xproj
#define TJ 5                          // outputs per thread (8 j-groups)
#define TT 4                          // timesteps per thread (16 t-groups)

#define NL 25                         // active lanes in k_out (own 4 outputs each)
#define NQ (HID / 2)                  // 20 k-pairs
#define OT 32                         // timesteps per k_out tile
#define NTILE (SEQ_LEN / OT)          // 4096 tiles
#define KOUT_GRID 592                 // persistent k_out blocks (~4/SM)

typedef unsigned long long u64;

// Scratch: device globals (no allocations allowed)
__device__ float g_xs[(SEQ_LEN + PF) * HID];  // input projections (+PF pad rows)
__device__ float g_h[SEQ_LEN * HID];          // hidden states per step

// ---- packed f32x2 helpers (sm_103a) ---------------------------------------
__device__ __forceinline__ u64 ffma2(u64 a, u64 b, u64 c) {
    u64 d; asm("fma.rn.f32x2 %0, %1, %2, %3;" : "=l"(d) : "l"(a), "l"(b), "l"(c));
    return d;
}
__device__ __forceinline__ u64 fadd2(u64 a, u64 b) {
    u64 d; asm("add.rn.f32x2 %0, %1, %2;" : "=l"(d) : "l"(a), "l"(b));
    return d;
}
__device__ __forceinline__ float hsum2(u64 a) {
    unsigned lo, hi; asm("mov.b64 {%0, %1}, %2;" : "=r"(lo), "=r"(hi) : "l"(a));
    return __uint_as_float(lo) + __uint_as_float(hi);
}
__device__ __forceinline__ float mufu_tanh(float x) {
    float r; asm("tanh.approx.f32 %0, %1;" : "=f"(r) : "f"(x));
    return r;
}

// ---------------------------------------------------------------------------
// Kernel 1: xs[t] = Wx @ s[t] + Wx_b — R13-proven 2-D register tile
// (5 outputs x 4 timesteps per thread).
// ---------------------------------------------------------------------------
__global__ void __launch_bounds__(128)
k_xproj(const float* __restrict__ s,
        const float* __restrict__ Wx,
        const float* __restrict__ Wxb) {
    __shared__ __align__(16) float sW[HID * IN];     // 16 KB
    __shared__ __align__(16) float sS[XTT * IN];     // 25.6 KB
    __shared__ float sb[HID];

    const int tid  = threadIdx.x;
    const int base = blockIdx.x * XTT;

    {
        const float4* wg = reinterpret_cast<const float4*>(Wx);
        float4*       ws = reinterpret_cast<float4*>(sW);
#pragma unroll
        for (int i = tid; i < HID * IN / 4; i += 128) ws[i] = wg[i];

        const float4* sg = reinterpret_cast<const float4*>(s + base * IN);
        float4*       ss = reinterpret_cast<float4*>(sS);
#pragma unroll
        for (int i = tid; i < XTT * IN / 4; i += 128) ss[i] = sg[i];

        if (tid < HID) sb[tid] = Wxb[tid];
    }
    __syncthreads();

    const int jg = tid & 7;            // 8 j-groups
    const int tg = tid >> 3;           // 16 t-groups
    const int j0 = jg * TJ;
    const int t0 = tg * TT;

    u64 acc[TJ][TT];
#pragma unroll
    for (int jj = 0; jj < TJ; jj++)
#pragma unroll
        for (int i = 0; i < TT; i++) acc[jj][i] = 0ull;

#pragma unroll
    for (int q = 0; q < IN / 4; q++) {       // 25 k-quads (16 B each)
        ulonglong2 w[TJ];
#pragma unroll
        for (int jj = 0; jj < TJ; jj++)
            w[jj] = *reinterpret_cast<const ulonglong2*>(sW + (j0 + jj) * IN + 4 * q);
        ulonglong2 sv[TT];
#pragma unroll
        for (int i = 0; i < TT; i++)
            sv[i] = *reinterpret_cast<const ulonglong2*>(sS + (t0 + i) * IN + 4 * q);
#pragma unroll
        for (int jj = 0; jj < TJ; jj++)
#pragma unroll
            for (int i = 0; i < TT; i++) {
                acc[jj][i] = ffma2((u64)w[jj].x, (u64)sv[i].x, acc[jj][i]);
                acc[jj][i] = ffma2((u64)w[jj].y, (u64)sv[i].y, acc[jj][i]);
            }
    }

#pragma unroll
    for (int jj = 0; jj < TJ; jj++) {
        const float bj = sb[j0 + jj];
#pragma unroll
        for (int i = 0; i < TT; i++)
            g_xs[(base + t0 + i) * HID + j0 + jj] = hsum2(acc[jj][i]) + bj;
    }
}

// ---------------------------------------------------------------------------
// Kernel 2: chunked recurrence — single warp per chunk (proven R12/R13).
// PDL prologue: Wh/bias loads are upstream-independent; gridDepSync before
// the first g_xs read.
// ---------------------------------------------------------------------------
__global__ void __launch_bounds__(32, 16)
k_recur(const float* __restrict__ Wh,  const float* __restrict__ Whb,
        const float* __restrict__ h0,  float* __restrict__ hfinal) {
    const int c    = blockIdx.x;
    const int lane = threadIdx.x;          // 0..31

    const bool act = (lane < HID / 2);     // 20 active lanes
    const int  j1  = act ? lane : (HID / 2 - 1);
    const int  j2  = j1 + HID / 2;

    const int t_own = c * CHLEN;
    const int t_lo  = (t_own >= BURN) ? (t_own - BURN) : 0;
    const int t_hi  = t_own + CHLEN;

    __shared__ __align__(16) float hs[2][HID];

    // -------- prologue (independent of k_xproj output) --------
    u64 w1[HID / 2], w2[HID / 2];
    {
        const longlong2* r1 = reinterpret_cast<const longlong2*>(Wh + j1 * HID);
        const longlong2* r2 = reinterpret_cast<const longlong2*>(Wh + j2 * HID);
#pragma unroll
        for (int q = 0; q < HID / 4; q++) {     // 10 iters
            longlong2 a = r1[q], b = r2[q];
            w1[2 * q] = (u64)a.x;  w1[2 * q + 1] = (u64)a.y;
            w2[2 * q] = (u64)b.x;  w2[2 * q + 1] = (u64)b.y;
        }
    }
    const float b1 = Whb[j1];
    const float b2 = Whb[j2];

    if (act) {
        hs[0][j1] = (c == 0) ? h0[j1] : 0.f;
        hs[0][j2] = (c == 0) ? h0[j2] : 0.f;
    }
    __syncwarp();

    // -------- wait for k_xproj completion, then consume g_xs --------
    cudaGridDependencySynchronize();

    float xf1[PF], xf2[PF];
#pragma unroll
    for (int k = 0; k < PF; k++) {
        xf1[k] = g_xs[(t_lo + k) * HID + j1];
        xf2[k] = g_xs[(t_lo + k) * HID + j2];
    }

    float v1 = 0.f, v2 = 0.f;

    for (int tb = t_lo; tb < t_hi; tb += PF) {
#pragma unroll
        for (int k = 0; k < PF; k++) {
            const int t = tb + k;                   // t&1 == k&1 (t_lo, PF even)
            const longlong2* hc = reinterpret_cast<const longlong2*>(hs[k & 1]);
            u64 a0 = 0ull, a1 = 0ull, c0 = 0ull, c1 = 0ull;
#pragma unroll
            for (int q = 0; q < 10; q += 2) {
                const longlong2 h01 = hc[q];
                const longlong2 h23 = hc[q + 1];
                a0 = ffma2(w1[2 * q],     (u64)h01.x, a0);
                a1 = ffma2(w1[2 * q + 1], (u64)h01.y, a1);
                c0 = ffma2(w2[2 * q],     (u64)h01.x, c0);
                c1 = ffma2(w2[2 * q + 1], (u64)h01.y, c1);
                a0 = ffma2(w1[2 * q + 2], (u64)h23.x, a0);
                a1 = ffma2(w1[2 * q + 3], (u64)h23.y, a1);
                c0 = ffma2(w2[2 * q + 2], (u64)h23.x, c0);
                c1 = ffma2(w2[2 * q + 3], (u64)h23.y, c1);
            }
            const float z1 = hsum2(fadd2(a0, a1)) + (xf1[k] + b1);
            const float z2 = hsum2(fadd2(c0, c1)) + (xf2[k] + b2);
            v1 = mufu_tanh(z1);
            v2 = mufu_tanh(z2);

            xf1[k] = g_xs[(tb + k + PF) * HID + j1];   // refill (padded array)
            xf2[k] = g_xs[(tb + k + PF) * HID + j2];

            if (act) {
                hs[(k & 1) ^ 1][j1] = v1;
                hs[(k & 1) ^ 1][j2] = v2;
                if (t >= t_own) {
                    g_h[t * HID + j1] = v1;
                    g_h[t * HID + j2] = v2;
                }
            }
            __syncwarp();
        }
    }
    if (act && c == NCHUNK - 1) {
        hfinal[j1] = v1;
        hfinal[j2] = v2;
    }
}

// ---------------------------------------------------------------------------
// Kernel 3: ys[t] = softmax(Wy h_t + Wy_b) — persistent blocks (proven v4).
// PDL prologue: stage sWq + biases (independent of k_recur), then gridDepSync
// before the first g_h read.
// ---------------------------------------------------------------------------
__global__ void __launch_bounds__(256)
k_out(const float* __restrict__ Wy, const float* __restrict__ Wyb,
      float* __restrict__ ys) {
    __shared__ __align__(16) u64   sWq[NQ * IN];     // 16 KB transposed weights
    __shared__ __align__(16) float sh[OT][HID];      // 5 KB h tile

    const int tid = threadIdx.x;

    // -------- prologue (independent of k_recur output) --------
    for (int m = tid; m < NQ * IN; m += 256) {
        const int q = m / IN, j = m % IN;
        sWq[m] = *reinterpret_cast<const u64*>(Wy + j * HID + 2 * q);
    }

    const int lane = tid & 31;
    const int wrp  = tid >> 5;               // 0..7 owns timesteps [4w, 4w+4)
    const bool act = (lane < NL);            // 25 active lanes
    const int  j0  = act ? lane : 0;         // outputs j0, j0+25, j0+50, j0+75

    float bias[4];
#pragma unroll
    for (int n = 0; n < 4; n++) bias[n] = Wyb[j0 + NL * n];

    const int l0 = wrp * 4;

    // -------- wait for k_recur completion, then consume g_h --------
    cudaGridDependencySynchronize();

    for (int tile = blockIdx.x; tile < NTILE; tile += KOUT_GRID) {
        const int base = tile * OT;

        __syncthreads();                     // protect sh reuse across iters
        {
            const float4* hg = reinterpret_cast<const float4*>(g_h + base * HID);
            float4*       h4 = reinterpret_cast<float4*>(&sh[0][0]);
#pragma unroll
            for (int i = tid; i < OT * HID / 4; i += 256) h4[i] = hg[i];
        }
        __syncthreads();

        u64 a[4][4];                         // [output n][timestep i]
#pragma unroll
        for (int n = 0; n < 4; n++)
#pragma unroll
            for (int i = 0; i < 4; i++) a[n][i] = 0ull;

#pragma unroll
        for (int q = 0; q < NQ; q++) {
            u64 w0 = sWq[q * IN + j0];
            u64 w1 = sWq[q * IN + j0 + NL];
            u64 w2 = sWq[q * IN + j0 + 2 * NL];
            u64 w3 = sWq[q * IN + j0 + 3 * NL];
#pragma unroll
            for (int i = 0; i < 4; i++) {
                const u64 hq =
                    *reinterpret_cast<const u64*>(&sh[l0 + i][2 * q]); // broadcast
                a[0][i] = ffma2(w0, hq, a[0][i]);
                a[1][i] = ffma2(w1, hq, a[1][i]);
                a[2][i] = ffma2(w2, hq, a[2][i]);
                a[3][i] = ffma2(w3, hq, a[3][i]);
            }
        }

#pragma unroll
        for (int i = 0; i < 4; i++) {
            float e[4];
            float sum = 0.f;
#pragma unroll
            for (int n = 0; n < 4; n++) {
                const float z = hsum2(a[n][i]) + bias[n];
                e[n] = act ? __expf(z) : 0.f;
                sum += e[n];
            }
#pragma unroll
            for (int o = 16; o > 0; o >>= 1)
                sum += __shfl_xor_sync(0xffffffffu, sum, o);
            const float inv = __frcp_rn(sum);
            if (act) {
                float* y = ys + (base + l0 + i) * IN;
#pragma unroll
                for (int n = 0; n < 4; n++)
                    y[j0 + NL * n] = e[n] * inv;     // coalesced
            }
        }
    }
}

// ---------------------------------------------------------------------------
extern "C" void kernel_launch(void* const* d_in, const int* in_sizes, int n_in,
                              void* d_out, int out_size) {
    const float* s   = (const float*)d_in[0];
    const float* h0  = (const float*)d_in[1];
    const float* Wx  = (const float*)d_in[2];
    const float* Wxb = (const float*)d_in[3];
    const float* Wh  = (const float*)d_in[4];
    const float* Whb = (const float*)d_in[5];
    const float* Wy  = (const float*)d_in[6];
    const float* Wyb = (const float*)d_in[7];

    float* out    = (float*)d_out;
    float* hfinal = out;           // [40]
    float* ys     = out + HID;     // [SEQ_LEN, 100]

    k_xproj<<<SEQ_LEN / XTT, 128>>>(s, Wx, Wxb);

    cudaLaunchAttribute attr[1];
    attr[0].id = cudaLaunchAttributeProgrammaticStreamSerialization;
    attr[0].val.programmaticStreamSerializationAllowed = 1;

    cudaLaunchConfig_t cfg_r = {};
    cfg_r.gridDim  = dim3(NCHUNK, 1, 1);
    cfg_r.blockDim = dim3(32, 1, 1);
    cfg_r.attrs    = attr;
    cfg_r.numAttrs = 1;
    cudaLaunchKernelEx(&cfg_r, k_recur, Wh, Whb, h0, hfinal);

    cudaLaunchConfig_t cfg_o = {};
    cfg_o.gridDim  = dim3(KOUT_GRID, 1, 1);
    cfg_o.blockDim = dim3(256, 1, 1);
    cfg_o.attrs    = attr;
    cfg_o.numAttrs = 1;
    cudaLaunchKernelEx(&cfg_o, k_out, Wy, Wyb, ys);
}